// round 8
// baseline (speedup 1.0000x reference)
#include <cuda_runtime.h>
#include <math.h>

#define N_NODES 8192
#define F_IN    512
#define F_OUT   256
#define NEG_MASK (-9e15f)

// ---------------- scratch (device globals; no allocs allowed) ----------------
__device__ float g_Wh[N_NODES * F_OUT];   // 8 MB
__device__ float g_u[N_NODES];            // exp(+0.5*t1_j)
__device__ float g_v[N_NODES];            // exp(+1.0*t1_j)
__device__ float g_p[N_NODES];            // c4 * exp(-0.5*t1_i)
__device__ float g_q[N_NODES];            // c5 * exp(-1.0*t1_i)
__device__ float g_coef[4];               // cA, cB, c4, c5

// ---------------- kernel 1: softmax(Mui) -> coefficients ----------------
__global__ void mui_kernel(const float* __restrict__ Mui) {
    if (threadIdx.x == 0 && blockIdx.x == 0) {
        float m = -INFINITY;
        #pragma unroll
        for (int i = 0; i < 6; i++) m = fmaxf(m, Mui[i]);
        float w[6], s = 0.f;
        #pragma unroll
        for (int i = 0; i < 6; i++) { w[i] = expf(Mui[i] - m); s += w[i]; }
        float inv = 1.f / s;
        #pragma unroll
        for (int i = 0; i < 6; i++) w[i] *= inv;
        g_coef[0] = w[0] + w[1] + w[2] + w[3];                  // cA (on G)
        g_coef[1] = 0.5f * (w[0] + w[1]) + 1.0f * (w[2] + w[3]); // cB (const)
        g_coef[2] = 256.0f * w[4];                               // c4
        g_coef[3] = 256.0f * w[5];                               // c5
    }
}

// ---------------- kernel 2: Wh = h @ W (f32 SGEMM, 128x128x16) ----------------
__global__ __launch_bounds__(256) void wh_gemm(const float* __restrict__ h,
                                               const float* __restrict__ W) {
    __shared__ float sA[16][128];  // A^T tile: [k][m]
    __shared__ float sB[16][128];  // B tile:   [k][n]
    const int tid = threadIdx.x;
    const int tx = tid & 15, ty = tid >> 4;
    const int n0 = blockIdx.x * 128;
    const int m0 = blockIdx.y * 128;

    float acc[8][8];
    #pragma unroll
    for (int i = 0; i < 8; i++)
        #pragma unroll
        for (int j = 0; j < 8; j++) acc[i][j] = 0.f;

    for (int k0 = 0; k0 < F_IN; k0 += 16) {
        #pragma unroll
        for (int l = 0; l < 2; l++) {
            int idx = tid + l * 256;          // 0..511
            // A: 128 rows x 4 float4 along k
            int row = idx >> 2;
            int kq  = idx & 3;
            float4 a = *(const float4*)&h[(size_t)(m0 + row) * F_IN + k0 + kq * 4];
            sA[kq * 4 + 0][row] = a.x;
            sA[kq * 4 + 1][row] = a.y;
            sA[kq * 4 + 2][row] = a.z;
            sA[kq * 4 + 3][row] = a.w;
            // B: 16 rows x 32 float4 along n
            int rowb = idx >> 5;
            int cq   = idx & 31;
            *(float4*)&sB[rowb][cq * 4] =
                *(const float4*)&W[(size_t)(k0 + rowb) * F_OUT + n0 + cq * 4];
        }
        __syncthreads();
        #pragma unroll
        for (int k = 0; k < 16; k++) {
            float a[8], b[8];
            *(float4*)(a)     = *(float4*)&sA[k][ty * 8];
            *(float4*)(a + 4) = *(float4*)&sA[k][ty * 8 + 4];
            *(float4*)(b)     = *(float4*)&sB[k][tx * 8];
            *(float4*)(b + 4) = *(float4*)&sB[k][tx * 8 + 4];
            #pragma unroll
            for (int i = 0; i < 8; i++)
                #pragma unroll
                for (int j = 0; j < 8; j++)
                    acc[i][j] = fmaf(a[i], b[j], acc[i][j]);
        }
        __syncthreads();
    }
    #pragma unroll
    for (int i = 0; i < 8; i++)
        #pragma unroll
        for (int j4 = 0; j4 < 2; j4++)
            *(float4*)&g_Wh[(size_t)(m0 + ty * 8 + i) * F_OUT + n0 + tx * 8 + j4 * 4] =
                *(float4*)&acc[i][j4 * 4];
}

// ---------------- kernel 3: per-node factors ----------------
__global__ void node_prep() {
    int i = blockIdx.x * blockDim.x + threadIdx.x;
    if (i < N_NODES) {
        float wh1 = g_Wh[(size_t)i * F_OUT + 1];
        float t1 = wh1 * wh1;
        g_u[i] = expf(0.5f * t1);
        g_v[i] = expf(t1);
        g_p[i] = g_coef[2] * expf(-0.5f * t1);
        g_q[i] = g_coef[3] * expf(-t1);
    }
}

// ---------------- kernel 4: fused flash attention ----------------
// BM=64 query rows per CTA, BN=64 key cols per tile, D=256.
// Threads: 256 as 16x16. Each thread: S block 4x4 (rows ty*4.., cols tx*4..),
// acc block 4 rows x 4 float4 col-groups (cols cc*64 + tx*4).
#define BM 64
#define BN 64
#define PAD_F4 65  // float4 row stride for Wh tiles (64 + 1 pad)

__global__ __launch_bounds__(256, 1) void flash_kernel(const int* __restrict__ adj,
                                                       float* __restrict__ out) {
    extern __shared__ float smem[];
    float* sWhI   = smem;                         // BM * 260 floats
    float* sWhJ   = sWhI + BM * PAD_F4 * 4;       // BN * 260
    float* sP     = sWhJ + BN * PAD_F4 * 4;       // 64 * 65
    int*   sAdj   = (int*)(sP + 64 * 65);         // 64 * 64
    float* sU     = (float*)(sAdj + 64 * 64);     // 64
    float* sV     = sU + 64;
    float* sPi    = sV + 64;
    float* sQi    = sPi + 64;
    float* sM     = sQi + 64;
    float* sL     = sM + 64;
    float* sScale = sL + 64;
    float* sMnew  = sScale + 64;

    const int tid = threadIdx.x;
    const int tx = tid & 15, ty = tid >> 4;
    const int i0 = blockIdx.x * BM;
    const float cA = g_coef[0], cB = g_coef[1];
    const float NEGINF = __int_as_float(0xff800000u);

    float4* sWhI4 = (float4*)sWhI;
    float4* sWhJ4 = (float4*)sWhJ;
    const float4* Wh4 = (const float4*)g_Wh;

    // load Wh_i tile (once)
    for (int idx = tid; idx < BM * 64; idx += 256) {
        int r = idx >> 6, c4 = idx & 63;
        sWhI4[r * PAD_F4 + c4] = Wh4[(size_t)(i0 + r) * 64 + c4];
    }
    if (tid < BM) {
        sPi[tid] = g_p[i0 + tid];
        sQi[tid] = g_q[i0 + tid];
        sM[tid] = NEGINF;
        sL[tid] = 0.f;
    }
    float4 acc[4][4];
    #pragma unroll
    for (int i = 0; i < 4; i++)
        #pragma unroll
        for (int c = 0; c < 4; c++) acc[i][c] = make_float4(0.f, 0.f, 0.f, 0.f);
    __syncthreads();

    const int4* adj4 = (const int4*)adj;
    int4* sAdj4 = (int4*)sAdj;

    for (int j0 = 0; j0 < N_NODES; j0 += BN) {
        // ---- load key tile ----
        for (int idx = tid; idx < BN * 64; idx += 256) {
            int r = idx >> 6, c4 = idx & 63;
            sWhJ4[r * PAD_F4 + c4] = Wh4[(size_t)(j0 + r) * 64 + c4];
        }
        for (int idx = tid; idx < BM * 16; idx += 256) {
            int r = idx >> 4, c4 = idx & 15;
            sAdj4[r * 16 + c4] = adj4[(size_t)(i0 + r) * (N_NODES / 4) + (j0 >> 2) + c4];
        }
        if (tid < BN) {
            sU[tid] = g_u[j0 + tid];
            sV[tid] = g_v[j0 + tid];
        }
        __syncthreads();

        // ---- S = Wh_i @ Wh_j^T (4x4 per thread) ----
        float s[4][4];
        #pragma unroll
        for (int i = 0; i < 4; i++)
            #pragma unroll
            for (int j = 0; j < 4; j++) s[i][j] = 0.f;
        {
            const float4* ai = sWhI4 + (ty * 4) * PAD_F4;
            const float4* bj = sWhJ4 + (tx * 4) * PAD_F4;
            #pragma unroll 4
            for (int k4 = 0; k4 < 64; k4++) {
                float4 a0 = ai[k4];
                float4 a1 = ai[PAD_F4 + k4];
                float4 a2 = ai[2 * PAD_F4 + k4];
                float4 a3 = ai[3 * PAD_F4 + k4];
                float4 b0 = bj[k4];
                float4 b1 = bj[PAD_F4 + k4];
                float4 b2 = bj[2 * PAD_F4 + k4];
                float4 b3 = bj[3 * PAD_F4 + k4];
                #define DOT4(S, A, B) \
                    S = fmaf(A.x, B.x, fmaf(A.y, B.y, fmaf(A.z, B.z, fmaf(A.w, B.w, S))))
                DOT4(s[0][0], a0, b0); DOT4(s[0][1], a0, b1); DOT4(s[0][2], a0, b2); DOT4(s[0][3], a0, b3);
                DOT4(s[1][0], a1, b0); DOT4(s[1][1], a1, b1); DOT4(s[1][2], a1, b2); DOT4(s[1][3], a1, b3);
                DOT4(s[2][0], a2, b0); DOT4(s[2][1], a2, b1); DOT4(s[2][2], a2, b2); DOT4(s[2][3], a2, b3);
                DOT4(s[3][0], a3, b0); DOT4(s[3][1], a3, b1); DOT4(s[3][2], a3, b2); DOT4(s[3][3], a3, b3);
                #undef DOT4
            }
        }

        // ---- scores + mask + row max ----
        float e[4][4];
        float rowmax[4];
        float u0 = sU[tx * 4 + 0], u1 = sU[tx * 4 + 1], u2 = sU[tx * 4 + 2], u3 = sU[tx * 4 + 3];
        float v0 = sV[tx * 4 + 0], v1 = sV[tx * 4 + 1], v2 = sV[tx * 4 + 2], v3 = sV[tx * 4 + 3];
        #pragma unroll
        for (int i = 0; i < 4; i++) {
            int r = ty * 4 + i;
            int4 mk = sAdj4[r * 16 + tx];
            float pu = sPi[r], qv = sQi[r];
            e[i][0] = (mk.x > 0) ? fmaf(cA, s[i][0], cB) + fmaf(pu, u0, qv * v0) : NEG_MASK;
            e[i][1] = (mk.y > 0) ? fmaf(cA, s[i][1], cB) + fmaf(pu, u1, qv * v1) : NEG_MASK;
            e[i][2] = (mk.z > 0) ? fmaf(cA, s[i][2], cB) + fmaf(pu, u2, qv * v2) : NEG_MASK;
            e[i][3] = (mk.w > 0) ? fmaf(cA, s[i][3], cB) + fmaf(pu, u3, qv * v3) : NEG_MASK;
            float m01 = fmaxf(e[i][0], e[i][1]);
            float m23 = fmaxf(e[i][2], e[i][3]);
            rowmax[i] = fmaxf(m01, m23);
        }
        #pragma unroll
        for (int i = 0; i < 4; i++) {
            #pragma unroll
            for (int off = 8; off >= 1; off >>= 1)
                rowmax[i] = fmaxf(rowmax[i], __shfl_xor_sync(0xffffffffu, rowmax[i], off));
        }
        if (tx == 0) {
            #pragma unroll
            for (int i = 0; i < 4; i++) {
                int r = ty * 4 + i;
                float mo = sM[r];
                float mn = fmaxf(mo, rowmax[i]);
                sMnew[r] = mn;
                sScale[r] = __expf(mo - mn);
            }
        }
        __syncthreads();

        // ---- weights, P tile, row sums, rescale acc ----
        float rowsum[4];
        #pragma unroll
        for (int i = 0; i < 4; i++) {
            int r = ty * 4 + i;
            float mn = sMnew[r];
            float w0 = __expf(e[i][0] - mn);
            float w1 = __expf(e[i][1] - mn);
            float w2 = __expf(e[i][2] - mn);
            float w3 = __expf(e[i][3] - mn);
            float* pr = &sP[r * 65 + tx * 4];
            pr[0] = w0; pr[1] = w1; pr[2] = w2; pr[3] = w3;
            rowsum[i] = (w0 + w1) + (w2 + w3);
        }
        #pragma unroll
        for (int i = 0; i < 4; i++) {
            #pragma unroll
            for (int off = 8; off >= 1; off >>= 1)
                rowsum[i] += __shfl_xor_sync(0xffffffffu, rowsum[i], off);
        }
        #pragma unroll
        for (int i = 0; i < 4; i++) {
            float sc = sScale[ty * 4 + i];
            #pragma unroll
            for (int c = 0; c < 4; c++) {
                acc[i][c].x *= sc; acc[i][c].y *= sc;
                acc[i][c].z *= sc; acc[i][c].w *= sc;
            }
        }
        if (tx == 0) {
            #pragma unroll
            for (int i = 0; i < 4; i++) {
                int r = ty * 4 + i;
                sL[r] = sL[r] * sScale[r] + rowsum[i];
                sM[r] = sMnew[r];
            }
        }
        __syncthreads();  // P + sWhJ ready for PV

        // ---- acc += P @ Wh_j ----
        {
            const float* p0r = &sP[(ty * 4 + 0) * 65];
            const float* p1r = &sP[(ty * 4 + 1) * 65];
            const float* p2r = &sP[(ty * 4 + 2) * 65];
            const float* p3r = &sP[(ty * 4 + 3) * 65];
            #pragma unroll 4
            for (int ss = 0; ss < BN; ss++) {
                float p0 = p0r[ss], p1 = p1r[ss], p2 = p2r[ss], p3 = p3r[ss];
                const float4* wr = sWhJ4 + ss * PAD_F4 + tx;
                #pragma unroll
                for (int cc = 0; cc < 4; cc++) {
                    float4 w = wr[cc * 16];
                    acc[0][cc].x = fmaf(p0, w.x, acc[0][cc].x);
                    acc[0][cc].y = fmaf(p0, w.y, acc[0][cc].y);
                    acc[0][cc].z = fmaf(p0, w.z, acc[0][cc].z);
                    acc[0][cc].w = fmaf(p0, w.w, acc[0][cc].w);
                    acc[1][cc].x = fmaf(p1, w.x, acc[1][cc].x);
                    acc[1][cc].y = fmaf(p1, w.y, acc[1][cc].y);
                    acc[1][cc].z = fmaf(p1, w.z, acc[1][cc].z);
                    acc[1][cc].w = fmaf(p1, w.w, acc[1][cc].w);
                    acc[2][cc].x = fmaf(p2, w.x, acc[2][cc].x);
                    acc[2][cc].y = fmaf(p2, w.y, acc[2][cc].y);
                    acc[2][cc].z = fmaf(p2, w.z, acc[2][cc].z);
                    acc[2][cc].w = fmaf(p2, w.w, acc[2][cc].w);
                    acc[3][cc].x = fmaf(p3, w.x, acc[3][cc].x);
                    acc[3][cc].y = fmaf(p3, w.y, acc[3][cc].y);
                    acc[3][cc].z = fmaf(p3, w.z, acc[3][cc].z);
                    acc[3][cc].w = fmaf(p3, w.w, acc[3][cc].w);
                }
            }
        }
        __syncthreads();  // before overwriting sWhJ / sAdj / sP next iter
    }

    // ---- epilogue: out = elu(acc / l) ----
    float4* out4 = (float4*)out;
    #pragma unroll
    for (int i = 0; i < 4; i++) {
        int r = ty * 4 + i;
        float inv = 1.0f / sL[r];
        #pragma unroll
        for (int cc = 0; cc < 4; cc++) {
            float4 a = acc[i][cc];
            a.x *= inv; a.y *= inv; a.z *= inv; a.w *= inv;
            a.x = (a.x > 0.f) ? a.x : expm1f(a.x);
            a.y = (a.y > 0.f) ? a.y : expm1f(a.y);
            a.z = (a.z > 0.f) ? a.z : expm1f(a.z);
            a.w = (a.w > 0.f) ? a.w : expm1f(a.w);
            out4[(size_t)(i0 + r) * 64 + cc * 16 + tx] = a;
        }
    }
}

// ---------------- launcher ----------------
extern "C" void kernel_launch(void* const* d_in, const int* in_sizes, int n_in,
                              void* d_out, int out_size) {
    const float* h   = (const float*)d_in[0];   // [8192, 512]
    const float* W   = (const float*)d_in[1];   // [512, 256]
    const float* Mui = (const float*)d_in[2];   // [6, 1]
    const int*   adj = (const int*)d_in[3];     // [8192, 8192]
    float* out = (float*)d_out;                 // [8192, 256]

    (void)in_sizes; (void)n_in; (void)out_size;

    const int smem_bytes = (BM * PAD_F4 * 4 + BN * PAD_F4 * 4 + 64 * 65) * 4
                         + 64 * 64 * 4 + 8 * 64 * 4;  // ~168 KB
    cudaFuncSetAttribute(flash_kernel, cudaFuncAttributeMaxDynamicSharedMemorySize,
                         smem_bytes);

    mui_kernel<<<1, 32>>>(Mui);
    wh_gemm<<<dim3(2, 64), 256>>>(h, W);
    node_prep<<<N_NODES / 256, 256>>>();
    flash_kernel<<<N_NODES / BM, 256, smem_bytes>>>(adj, out);
}

// round 10
// speedup vs baseline: 2.2182x; 2.2182x over previous
#include <cuda_runtime.h>
#include <math.h>
#include <stdint.h>

#define N_NODES 8192
#define F_IN    512
#define F_OUT   256
#define NEG_MASK (-9e15f)

__device__ float g_Wh[N_NODES * F_OUT];
__device__ float g_u[N_NODES], g_v[N_NODES], g_p[N_NODES], g_q[N_NODES];
__device__ float g_coef[4];

__device__ __forceinline__ uint32_t f2tf(float x) {
    uint32_t u; asm("cvt.rna.tf32.f32 %0, %1;" : "=r"(u) : "f"(x)); return u;
}
__device__ __forceinline__ void cvt2(float x, uint32_t& h, uint32_t& l) {
    h = f2tf(x);
    l = f2tf(x - __uint_as_float(h));
}
#define MMA(c, A, B) \
    asm volatile("mma.sync.aligned.m16n8k8.row.col.f32.tf32.tf32.f32 " \
        "{%0,%1,%2,%3},{%4,%5,%6,%7},{%8,%9},{%0,%1,%2,%3};" \
        : "+f"((c)[0]), "+f"((c)[1]), "+f"((c)[2]), "+f"((c)[3]) \
        : "r"((A)[0]), "r"((A)[1]), "r"((A)[2]), "r"((A)[3]), \
          "r"((B)[0]), "r"((B)[1]))

// ---------------- kernel 1: softmax(Mui) -> coefficients ----------------
__global__ void mui_kernel(const float* __restrict__ Mui) {
    if (threadIdx.x == 0 && blockIdx.x == 0) {
        float m = -INFINITY;
        for (int i = 0; i < 6; i++) m = fmaxf(m, Mui[i]);
        float w[6], s = 0.f;
        for (int i = 0; i < 6; i++) { w[i] = expf(Mui[i] - m); s += w[i]; }
        float inv = 1.f / s;
        for (int i = 0; i < 6; i++) w[i] *= inv;
        g_coef[0] = w[0] + w[1] + w[2] + w[3];
        g_coef[1] = 0.5f * (w[0] + w[1]) + (w[2] + w[3]);
        g_coef[2] = 256.0f * w[4];
        g_coef[3] = 256.0f * w[5];
    }
}

// ---------------- kernel 2: Wh = h @ W (f32 SGEMM) ----------------
__global__ __launch_bounds__(256) void wh_gemm(const float* __restrict__ h,
                                               const float* __restrict__ W) {
    __shared__ float sA[16][128];
    __shared__ float sB[16][128];
    const int tid = threadIdx.x, tx = tid & 15, ty = tid >> 4;
    const int n0 = blockIdx.x * 128, m0 = blockIdx.y * 128;
    float acc[8][8];
    #pragma unroll
    for (int i = 0; i < 8; i++)
        #pragma unroll
        for (int j = 0; j < 8; j++) acc[i][j] = 0.f;
    for (int k0 = 0; k0 < F_IN; k0 += 16) {
        #pragma unroll
        for (int l = 0; l < 2; l++) {
            int idx = tid + l * 256;
            int row = idx >> 2, kq = idx & 3;
            float4 a = *(const float4*)&h[(size_t)(m0 + row) * F_IN + k0 + kq * 4];
            sA[kq * 4 + 0][row] = a.x; sA[kq * 4 + 1][row] = a.y;
            sA[kq * 4 + 2][row] = a.z; sA[kq * 4 + 3][row] = a.w;
            int rowb = idx >> 5, cq = idx & 31;
            *(float4*)&sB[rowb][cq * 4] =
                *(const float4*)&W[(size_t)(k0 + rowb) * F_OUT + n0 + cq * 4];
        }
        __syncthreads();
        #pragma unroll
        for (int k = 0; k < 16; k++) {
            float a[8], b[8];
            *(float4*)(a) = *(float4*)&sA[k][ty * 8];
            *(float4*)(a + 4) = *(float4*)&sA[k][ty * 8 + 4];
            *(float4*)(b) = *(float4*)&sB[k][tx * 8];
            *(float4*)(b + 4) = *(float4*)&sB[k][tx * 8 + 4];
            #pragma unroll
            for (int i = 0; i < 8; i++)
                #pragma unroll
                for (int j = 0; j < 8; j++) acc[i][j] = fmaf(a[i], b[j], acc[i][j]);
        }
        __syncthreads();
    }
    #pragma unroll
    for (int i = 0; i < 8; i++)
        #pragma unroll
        for (int j4 = 0; j4 < 2; j4++)
            *(float4*)&g_Wh[(size_t)(m0 + ty * 8 + i) * F_OUT + n0 + tx * 8 + j4 * 4] =
                *(float4*)&acc[i][j4 * 4];
}

// ---------------- kernel 3: per-node factors ----------------
__global__ void node_prep() {
    int i = blockIdx.x * blockDim.x + threadIdx.x;
    if (i < N_NODES) {
        float wh1 = g_Wh[(size_t)i * F_OUT + 1];
        float t1 = wh1 * wh1;
        g_u[i] = expf(0.5f * t1);
        g_v[i] = expf(t1);
        g_p[i] = g_coef[2] * expf(-0.5f * t1);
        g_q[i] = g_coef[3] * expf(-t1);
    }
}

// ---------------- kernel 4: fused flash attention (mma.sync tf32) ----------------
// BM=64 rows/CTA, BN=64 keys/tile, D=256. 8 warps: warp_m=wid&3 (16-row strip),
// warp_n=wid>>2 (32 S-cols / 128 O-cols strip). S in 3xTF32, PV in 1xTF32.
#define SWI 264   // Wh tile row stride (floats): 264 % 32 == 8 -> conflict-free frags
#define SPJ 72    // P row stride
#define SAJ 68    // adj row stride (ints)
#define OFF_WHJ  16896
#define OFF_P    33792
#define OFF_ADJ  38400
#define OFF_U    42752
#define OFF_V    42816
#define OFF_M    42880
#define OFF_SC   42944
#define OFF_PART 43008
#define SMEM_FLASH (43136 * 4)

__global__ __launch_bounds__(256, 1) void flash_mma(const int* __restrict__ adj,
                                                    float* __restrict__ out) {
    extern __shared__ float sm[];
    float* sWhi = sm;
    float* sWhj = sm + OFF_WHJ;
    float* sP   = sm + OFF_P;
    int*   sAdj = (int*)(sm + OFF_ADJ);
    float* sU = sm + OFF_U;  float* sV  = sm + OFF_V;
    float* sM = sm + OFF_M;  float* sSc = sm + OFF_SC;
    float* sPart = sm + OFF_PART;

    const int tid = threadIdx.x, lane = tid & 31, wid = tid >> 5;
    const int wm = wid & 3, wn = wid >> 2;
    const int g = lane >> 2, t = lane & 3;
    const int i0 = blockIdx.x * 64;
    const int r0 = wm * 16 + g, r1 = r0 + 8;
    const int wn32 = wn * 32, wn128 = wn * 128;

    for (int x = tid; x < 64 * 64; x += 256) {
        int row = x >> 6, c4 = x & 63;
        *(float4*)(sWhi + row * SWI + c4 * 4) =
            *(const float4*)(g_Wh + (size_t)(i0 + row) * F_OUT + c4 * 4);
    }
    if (tid < 64) sM[tid] = -INFINITY;

    const float cA = g_coef[0], cB = g_coef[1];
    const float pr0 = g_p[i0 + r0], qr0 = g_q[i0 + r0];
    const float pr1 = g_p[i0 + r1], qr1 = g_q[i0 + r1];

    float O[16][4];
    #pragma unroll
    for (int n = 0; n < 16; n++) { O[n][0] = O[n][1] = O[n][2] = O[n][3] = 0.f; }
    float lw0 = 0.f, lw1 = 0.f;
    __syncthreads();

    for (int j0 = 0; j0 < N_NODES; j0 += 64) {
        for (int x = tid; x < 64 * 64; x += 256) {
            int row = x >> 6, c4 = x & 63;
            *(float4*)(sWhj + row * SWI + c4 * 4) =
                *(const float4*)(g_Wh + (size_t)(j0 + row) * F_OUT + c4 * 4);
        }
        for (int x = tid; x < 64 * 16; x += 256) {
            int row = x >> 4, c4 = x & 15;
            *(int4*)(sAdj + row * SAJ + c4 * 4) =
                *(const int4*)(adj + (size_t)(i0 + row) * N_NODES + j0 + c4 * 4);
        }
        if (tid < 64) { sU[tid] = g_u[j0 + tid]; sV[tid] = g_v[j0 + tid]; }
        __syncthreads();

        // ---- S = Whi . Whj^T, 3xTF32 ----
        float sS[4][4];
        #pragma unroll
        for (int n = 0; n < 4; n++) sS[n][0] = sS[n][1] = sS[n][2] = sS[n][3] = 0.f;
        const float* wi0 = sWhi + r0 * SWI;
        const float* wi1 = sWhi + r1 * SWI;
        #pragma unroll 4
        for (int ks = 0; ks < 32; ks++) {
            int k0 = ks * 8;
            uint32_t AH[4], AL[4];
            cvt2(wi0[k0 + t],     AH[0], AL[0]);
            cvt2(wi1[k0 + t],     AH[1], AL[1]);
            cvt2(wi0[k0 + t + 4], AH[2], AL[2]);
            cvt2(wi1[k0 + t + 4], AH[3], AL[3]);
            #pragma unroll
            for (int nt = 0; nt < 4; nt++) {
                const float* wj = sWhj + (wn32 + nt * 8 + g) * SWI;
                uint32_t BH[2], BL[2];
                cvt2(wj[k0 + t],     BH[0], BL[0]);
                cvt2(wj[k0 + t + 4], BH[1], BL[1]);
                MMA(sS[nt], AH, BH);
                MMA(sS[nt], AH, BL);
                MMA(sS[nt], AL, BH);
            }
        }

        // ---- logits + row max ----
        float e[4][4];
        float rm0 = -INFINITY, rm1 = -INFINITY;
        #pragma unroll
        for (int nt = 0; nt < 4; nt++) {
            int jl = wn32 + nt * 8 + 2 * t;
            float u0 = sU[jl], u1 = sU[jl + 1], v0 = sV[jl], v1 = sV[jl + 1];
            int a00 = sAdj[r0 * SAJ + jl], a01 = sAdj[r0 * SAJ + jl + 1];
            int a10 = sAdj[r1 * SAJ + jl], a11 = sAdj[r1 * SAJ + jl + 1];
            e[nt][0] = a00 > 0 ? fmaf(cA, sS[nt][0], cB) + fmaf(pr0, u0, qr0 * v0) : NEG_MASK;
            e[nt][1] = a01 > 0 ? fmaf(cA, sS[nt][1], cB) + fmaf(pr0, u1, qr0 * v1) : NEG_MASK;
            e[nt][2] = a10 > 0 ? fmaf(cA, sS[nt][2], cB) + fmaf(pr1, u0, qr1 * v0) : NEG_MASK;
            e[nt][3] = a11 > 0 ? fmaf(cA, sS[nt][3], cB) + fmaf(pr1, u1, qr1 * v1) : NEG_MASK;
            rm0 = fmaxf(rm0, fmaxf(e[nt][0], e[nt][1]));
            rm1 = fmaxf(rm1, fmaxf(e[nt][2], e[nt][3]));
        }
        rm0 = fmaxf(rm0, __shfl_xor_sync(~0u, rm0, 1));
        rm0 = fmaxf(rm0, __shfl_xor_sync(~0u, rm0, 2));
        rm1 = fmaxf(rm1, __shfl_xor_sync(~0u, rm1, 1));
        rm1 = fmaxf(rm1, __shfl_xor_sync(~0u, rm1, 2));
        if (t == 0) { sPart[wn * 64 + r0] = rm0; sPart[wn * 64 + r1] = rm1; }
        __syncthreads();
        if (wn == 0 && t == 0) {
            float mo0 = sM[r0], mn0 = fmaxf(mo0, fmaxf(sPart[r0], sPart[64 + r0]));
            sSc[r0] = __expf(mo0 - mn0); sM[r0] = mn0;
            float mo1 = sM[r1], mn1 = fmaxf(mo1, fmaxf(sPart[r1], sPart[64 + r1]));
            sSc[r1] = __expf(mo1 - mn1); sM[r1] = mn1;
        }
        __syncthreads();
        float sc0 = sSc[r0], sc1 = sSc[r1];
        float m0 = sM[r0], m1 = sM[r1];
        lw0 *= sc0; lw1 *= sc1;
        #pragma unroll
        for (int n = 0; n < 16; n++) {
            O[n][0] *= sc0; O[n][1] *= sc0; O[n][2] *= sc1; O[n][3] *= sc1;
        }
        uint32_t* sPu = (uint32_t*)sP;
        #pragma unroll
        for (int nt = 0; nt < 4; nt++) {
            int jl = wn32 + nt * 8 + 2 * t;
            uint32_t q0 = f2tf(__expf(e[nt][0] - m0));
            uint32_t q1 = f2tf(__expf(e[nt][1] - m0));
            uint32_t q2 = f2tf(__expf(e[nt][2] - m1));
            uint32_t q3 = f2tf(__expf(e[nt][3] - m1));
            lw0 += __uint_as_float(q0) + __uint_as_float(q1);
            lw1 += __uint_as_float(q2) + __uint_as_float(q3);
            *(uint2*)(sPu + r0 * SPJ + jl) = make_uint2(q0, q1);
            *(uint2*)(sPu + r1 * SPJ + jl) = make_uint2(q2, q3);
        }
        __syncthreads();

        // ---- O += P . Whj (1xTF32) ----
        const uint32_t* p0 = (const uint32_t*)sP + r0 * SPJ;
        const uint32_t* p1 = (const uint32_t*)sP + r1 * SPJ;
        #pragma unroll
        for (int ks = 0; ks < 8; ks++) {
            int k0 = ks * 8;
            uint32_t A[4] = { p0[k0 + t], p1[k0 + t], p0[k0 + t + 4], p1[k0 + t + 4] };
            #pragma unroll
            for (int nt = 0; nt < 16; nt++) {
                int n0 = wn128 + nt * 8 + g;
                uint32_t B[2] = { f2tf(sWhj[(k0 + t) * SWI + n0]),
                                  f2tf(sWhj[(k0 + t + 4) * SWI + n0]) };
                MMA(O[nt], A, B);
            }
        }
        __syncthreads();
    }

    // ---- epilogue ----
    lw0 += __shfl_xor_sync(~0u, lw0, 1); lw0 += __shfl_xor_sync(~0u, lw0, 2);
    lw1 += __shfl_xor_sync(~0u, lw1, 1); lw1 += __shfl_xor_sync(~0u, lw1, 2);
    if (t == 0) { sPart[wn * 64 + r0] = lw0; sPart[wn * 64 + r1] = lw1; }
    __syncthreads();
    float inv0 = 1.f / (sPart[r0] + sPart[64 + r0]);
    float inv1 = 1.f / (sPart[r1] + sPart[64 + r1]);
    #pragma unroll
    for (int nt = 0; nt < 16; nt++) {
        int col = wn128 + nt * 8 + 2 * t;
        float o0 = O[nt][0] * inv0, o1 = O[nt][1] * inv0;
        float o2 = O[nt][2] * inv1, o3 = O[nt][3] * inv1;
        o0 = o0 > 0.f ? o0 : expm1f(o0);
        o1 = o1 > 0.f ? o1 : expm1f(o1);
        o2 = o2 > 0.f ? o2 : expm1f(o2);
        o3 = o3 > 0.f ? o3 : expm1f(o3);
        *(float2*)(out + (size_t)(i0 + r0) * F_OUT + col) = make_float2(o0, o1);
        *(float2*)(out + (size_t)(i0 + r1) * F_OUT + col) = make_float2(o2, o3);
    }
}

// ---------------- launcher ----------------
extern "C" void kernel_launch(void* const* d_in, const int* in_sizes, int n_in,
                              void* d_out, int out_size) {
    const float* h   = (const float*)d_in[0];
    const float* W   = (const float*)d_in[1];
    const float* Mui = (const float*)d_in[2];
    const int*   adj = (const int*)d_in[3];
    float* out = (float*)d_out;
    (void)in_sizes; (void)n_in; (void)out_size;

    cudaFuncSetAttribute(flash_mma, cudaFuncAttributeMaxDynamicSharedMemorySize,
                         SMEM_FLASH);

    mui_kernel<<<1, 32>>>(Mui);
    wh_gemm<<<dim3(2, 64), 256>>>(h, W);
    node_prep<<<N_NODES / 256, 256>>>();
    flash_mma<<<N_NODES / 64, 256, SMEM_FLASH>>>(adj, out);
}

// round 11
// speedup vs baseline: 2.4855x; 1.1205x over previous
#include <cuda_runtime.h>
#include <math.h>
#include <stdint.h>

#define N_NODES 8192
#define F_IN    512
#define F_OUT   256
#define NEG_MASK (-9e15f)

__device__ float g_Wh[N_NODES * F_OUT];
__device__ float g_WhH[N_NODES * F_OUT];   // tf32-rounded hi
__device__ float g_WhL[N_NODES * F_OUT];   // tf32 residual lo
__device__ float g_u[N_NODES], g_v[N_NODES], g_p[N_NODES], g_q[N_NODES];
__device__ float g_coef[4];

__device__ __forceinline__ uint32_t f2tf(float x) {
    uint32_t u; asm("cvt.rna.tf32.f32 %0, %1;" : "=r"(u) : "f"(x)); return u;
}
__device__ __forceinline__ void cvt2(float x, uint32_t& h, uint32_t& l) {
    h = f2tf(x);
    l = f2tf(x - __uint_as_float(h));
}
#define MMA(c, A, B) \
    asm volatile("mma.sync.aligned.m16n8k8.row.col.f32.tf32.tf32.f32 " \
        "{%0,%1,%2,%3},{%4,%5,%6,%7},{%8,%9},{%0,%1,%2,%3};" \
        : "+f"((c)[0]), "+f"((c)[1]), "+f"((c)[2]), "+f"((c)[3]) \
        : "r"((A)[0]), "r"((A)[1]), "r"((A)[2]), "r"((A)[3]), \
          "r"((B)[0]), "r"((B)[1]))

// ---------------- kernel 1: softmax(Mui) ----------------
__global__ void mui_kernel(const float* __restrict__ Mui) {
    if (threadIdx.x == 0 && blockIdx.x == 0) {
        float m = -INFINITY;
        for (int i = 0; i < 6; i++) m = fmaxf(m, Mui[i]);
        float w[6], s = 0.f;
        for (int i = 0; i < 6; i++) { w[i] = expf(Mui[i] - m); s += w[i]; }
        float inv = 1.f / s;
        for (int i = 0; i < 6; i++) w[i] *= inv;
        g_coef[0] = w[0] + w[1] + w[2] + w[3];
        g_coef[1] = 0.5f * (w[0] + w[1]) + (w[2] + w[3]);
        g_coef[2] = 256.0f * w[4];
        g_coef[3] = 256.0f * w[5];
    }
}

// ---------------- kernel 2: Wh = h @ W + tf32 hi/lo split ----------------
__global__ __launch_bounds__(256) void wh_gemm(const float* __restrict__ h,
                                               const float* __restrict__ W) {
    __shared__ float sA[16][128];
    __shared__ float sB[16][128];
    const int tid = threadIdx.x, tx = tid & 15, ty = tid >> 4;
    const int n0 = blockIdx.x * 128, m0 = blockIdx.y * 128;
    float acc[8][8];
    #pragma unroll
    for (int i = 0; i < 8; i++)
        #pragma unroll
        for (int j = 0; j < 8; j++) acc[i][j] = 0.f;
    for (int k0 = 0; k0 < F_IN; k0 += 16) {
        #pragma unroll
        for (int l = 0; l < 2; l++) {
            int idx = tid + l * 256;
            int row = idx >> 2, kq = idx & 3;
            float4 a = *(const float4*)&h[(size_t)(m0 + row) * F_IN + k0 + kq * 4];
            sA[kq * 4 + 0][row] = a.x; sA[kq * 4 + 1][row] = a.y;
            sA[kq * 4 + 2][row] = a.z; sA[kq * 4 + 3][row] = a.w;
            int rowb = idx >> 5, cq = idx & 31;
            *(float4*)&sB[rowb][cq * 4] =
                *(const float4*)&W[(size_t)(k0 + rowb) * F_OUT + n0 + cq * 4];
        }
        __syncthreads();
        #pragma unroll
        for (int k = 0; k < 16; k++) {
            float a[8], b[8];
            *(float4*)(a) = *(float4*)&sA[k][ty * 8];
            *(float4*)(a + 4) = *(float4*)&sA[k][ty * 8 + 4];
            *(float4*)(b) = *(float4*)&sB[k][tx * 8];
            *(float4*)(b + 4) = *(float4*)&sB[k][tx * 8 + 4];
            #pragma unroll
            for (int i = 0; i < 8; i++)
                #pragma unroll
                for (int j = 0; j < 8; j++) acc[i][j] = fmaf(a[i], b[j], acc[i][j]);
        }
        __syncthreads();
    }
    #pragma unroll
    for (int i = 0; i < 8; i++)
        #pragma unroll
        for (int j4 = 0; j4 < 2; j4++) {
            size_t base = (size_t)(m0 + ty * 8 + i) * F_OUT + n0 + tx * 8 + j4 * 4;
            float4 v = *(float4*)&acc[i][j4 * 4];
            *(float4*)&g_Wh[base] = v;
            float4 hv, lv;
            uint32_t hb, lb;
            cvt2(v.x, hb, lb); hv.x = __uint_as_float(hb); lv.x = __uint_as_float(lb);
            cvt2(v.y, hb, lb); hv.y = __uint_as_float(hb); lv.y = __uint_as_float(lb);
            cvt2(v.z, hb, lb); hv.z = __uint_as_float(hb); lv.z = __uint_as_float(lb);
            cvt2(v.w, hb, lb); hv.w = __uint_as_float(hb); lv.w = __uint_as_float(lb);
            *(float4*)&g_WhH[base] = hv;
            *(float4*)&g_WhL[base] = lv;
        }
}

// ---------------- kernel 3: per-node factors ----------------
__global__ void node_prep() {
    int i = blockIdx.x * blockDim.x + threadIdx.x;
    if (i < N_NODES) {
        float wh1 = g_Wh[(size_t)i * F_OUT + 1];
        float t1 = wh1 * wh1;
        g_u[i] = expf(0.5f * t1);
        g_v[i] = expf(t1);
        g_p[i] = g_coef[2] * expf(-0.5f * t1);
        g_q[i] = g_coef[3] * expf(-t1);
    }
}

// ---------------- kernel 4: fused flash (mma.sync tf32, 512 thr) ----------------
// 16 warps: wm=wid&3 (16-row strip), wn=wid>>2 (16 S-cols / 64 O-cols strip).
// S in 3xTF32 (B hi/lo pre-split), PV in 1xTF32 (B = hi tile directly).
#define SWI 260            // Wh tile stride: 260%32==4 -> 4g+t conflict-free
#define SPJ 68             // P stride: conflict-free PV-A
#define OFF_WHJH 16640
#define OFF_WHJL 33280
#define OFF_P    49920
#define OFF_U    54272
#define OFF_V    54336
#define OFF_M    54400
#define OFF_SC   54464
#define OFF_PART 54528
#define SMEM_FLASH (54784 * 4)

__global__ __launch_bounds__(512, 1) void flash_mma(const int* __restrict__ adj,
                                                    float* __restrict__ out) {
    extern __shared__ float sm[];
    float* sWhi  = sm;
    float* sWhjH = sm + OFF_WHJH;
    float* sWhjL = sm + OFF_WHJL;
    float* sP    = sm + OFF_P;
    float* sU = sm + OFF_U;  float* sV  = sm + OFF_V;
    float* sM = sm + OFF_M;  float* sSc = sm + OFF_SC;
    float* sPart = sm + OFF_PART;

    const int tid = threadIdx.x, lane = tid & 31, wid = tid >> 5;
    const int wm = wid & 3, wn = wid >> 2;          // wn 0..3
    const int g = lane >> 2, t = lane & 3;
    const int i0 = blockIdx.x * 64;
    const int r0 = wm * 16 + g, r1 = r0 + 8;
    const int wn16 = wn * 16, wn64 = wn * 64;

    for (int x = tid; x < 64 * 64; x += 512) {
        int row = x >> 6, c4 = x & 63;
        *(float4*)(sWhi + row * SWI + c4 * 4) =
            *(const float4*)(g_Wh + (size_t)(i0 + row) * F_OUT + c4 * 4);
    }
    if (tid < 64) sM[tid] = -INFINITY;

    const float cA = g_coef[0], cB = g_coef[1];
    const float pr0 = g_p[i0 + r0], qr0 = g_q[i0 + r0];
    const float pr1 = g_p[i0 + r1], qr1 = g_q[i0 + r1];
    const int* arow0 = adj + (size_t)(i0 + r0) * N_NODES;
    const int* arow1 = adj + (size_t)(i0 + r1) * N_NODES;

    float O[8][4];
    #pragma unroll
    for (int n = 0; n < 8; n++) { O[n][0] = O[n][1] = O[n][2] = O[n][3] = 0.f; }
    float lw0 = 0.f, lw1 = 0.f;
    __syncthreads();

    for (int j0 = 0; j0 < N_NODES; j0 += 64) {
        for (int x = tid; x < 64 * 64; x += 512) {
            int row = x >> 6, c4 = x & 63;
            size_t src = (size_t)(j0 + row) * F_OUT + c4 * 4;
            *(float4*)(sWhjH + row * SWI + c4 * 4) = *(const float4*)(g_WhH + src);
            *(float4*)(sWhjL + row * SWI + c4 * 4) = *(const float4*)(g_WhL + src);
        }
        if (tid < 64) { sU[tid] = g_u[j0 + tid]; sV[tid] = g_v[j0 + tid]; }
        __syncthreads();

        // ---- S = Whi . Whj^T (3xTF32; B pre-split) ----
        float sS[2][4];
        #pragma unroll
        for (int n = 0; n < 2; n++) sS[n][0] = sS[n][1] = sS[n][2] = sS[n][3] = 0.f;
        const float* wi0 = sWhi + r0 * SWI;
        const float* wi1 = sWhi + r1 * SWI;
        #pragma unroll 4
        for (int ks = 0; ks < 32; ks++) {
            int k0 = ks * 8;
            uint32_t AH[4], AL[4];
            cvt2(wi0[k0 + t],     AH[0], AL[0]);
            cvt2(wi1[k0 + t],     AH[1], AL[1]);
            cvt2(wi0[k0 + t + 4], AH[2], AL[2]);
            cvt2(wi1[k0 + t + 4], AH[3], AL[3]);
            #pragma unroll
            for (int nt = 0; nt < 2; nt++) {
                int jr = (wn16 + nt * 8 + g) * SWI;
                uint32_t BH[2] = { __float_as_uint(sWhjH[jr + k0 + t]),
                                   __float_as_uint(sWhjH[jr + k0 + t + 4]) };
                uint32_t BL[2] = { __float_as_uint(sWhjL[jr + k0 + t]),
                                   __float_as_uint(sWhjL[jr + k0 + t + 4]) };
                MMA(sS[nt], AH, BH);
                MMA(sS[nt], AH, BL);
                MMA(sS[nt], AL, BH);
            }
        }

        // ---- logits + row max ----
        float e[2][4];
        float rm0 = -INFINITY, rm1 = -INFINITY;
        #pragma unroll
        for (int nt = 0; nt < 2; nt++) {
            int jl = wn16 + nt * 8 + 2 * t;
            float2 uu = *(const float2*)(sU + jl);
            float2 vv = *(const float2*)(sV + jl);
            int2 a0 = *(const int2*)(arow0 + j0 + jl);
            int2 a1 = *(const int2*)(arow1 + j0 + jl);
            e[nt][0] = a0.x > 0 ? fmaf(cA, sS[nt][0], cB) + fmaf(pr0, uu.x, qr0 * vv.x) : NEG_MASK;
            e[nt][1] = a0.y > 0 ? fmaf(cA, sS[nt][1], cB) + fmaf(pr0, uu.y, qr0 * vv.y) : NEG_MASK;
            e[nt][2] = a1.x > 0 ? fmaf(cA, sS[nt][2], cB) + fmaf(pr1, uu.x, qr1 * vv.x) : NEG_MASK;
            e[nt][3] = a1.y > 0 ? fmaf(cA, sS[nt][3], cB) + fmaf(pr1, uu.y, qr1 * vv.y) : NEG_MASK;
            rm0 = fmaxf(rm0, fmaxf(e[nt][0], e[nt][1]));
            rm1 = fmaxf(rm1, fmaxf(e[nt][2], e[nt][3]));
        }
        rm0 = fmaxf(rm0, __shfl_xor_sync(~0u, rm0, 1));
        rm0 = fmaxf(rm0, __shfl_xor_sync(~0u, rm0, 2));
        rm1 = fmaxf(rm1, __shfl_xor_sync(~0u, rm1, 1));
        rm1 = fmaxf(rm1, __shfl_xor_sync(~0u, rm1, 2));
        if (t == 0) { sPart[wn * 64 + r0] = rm0; sPart[wn * 64 + r1] = rm1; }
        __syncthreads();
        if (wn == 0 && t == 0) {
            float mo0 = sM[r0];
            float mn0 = fmaxf(fmaxf(mo0, fmaxf(sPart[r0], sPart[64 + r0])),
                              fmaxf(sPart[128 + r0], sPart[192 + r0]));
            sSc[r0] = __expf(mo0 - mn0); sM[r0] = mn0;
            float mo1 = sM[r1];
            float mn1 = fmaxf(fmaxf(mo1, fmaxf(sPart[r1], sPart[64 + r1])),
                              fmaxf(sPart[128 + r1], sPart[192 + r1]));
            sSc[r1] = __expf(mo1 - mn1); sM[r1] = mn1;
        }
        __syncthreads();
        float sc0 = sSc[r0], sc1 = sSc[r1];
        float m0 = sM[r0], m1 = sM[r1];
        lw0 *= sc0; lw1 *= sc1;
        #pragma unroll
        for (int n = 0; n < 8; n++) {
            O[n][0] *= sc0; O[n][1] *= sc0; O[n][2] *= sc1; O[n][3] *= sc1;
        }
        uint32_t* sPu = (uint32_t*)sP;
        #pragma unroll
        for (int nt = 0; nt < 2; nt++) {
            int jl = wn16 + nt * 8 + 2 * t;
            uint32_t q0 = f2tf(__expf(e[nt][0] - m0));
            uint32_t q1 = f2tf(__expf(e[nt][1] - m0));
            uint32_t q2 = f2tf(__expf(e[nt][2] - m1));
            uint32_t q3 = f2tf(__expf(e[nt][3] - m1));
            lw0 += __uint_as_float(q0) + __uint_as_float(q1);
            lw1 += __uint_as_float(q2) + __uint_as_float(q3);
            *(uint2*)(sPu + r0 * SPJ + jl) = make_uint2(q0, q1);
            *(uint2*)(sPu + r1 * SPJ + jl) = make_uint2(q2, q3);
        }
        __syncthreads();

        // ---- O += P . Whj (1xTF32, B = hi tile) ----
        const uint32_t* p0 = (const uint32_t*)sP + r0 * SPJ;
        const uint32_t* p1 = (const uint32_t*)sP + r1 * SPJ;
        #pragma unroll
        for (int ks = 0; ks < 8; ks++) {
            int k0 = ks * 8;
            uint32_t A[4] = { p0[k0 + t], p1[k0 + t], p0[k0 + t + 4], p1[k0 + t + 4] };
            #pragma unroll
            for (int nt = 0; nt < 8; nt++) {
                int n0 = wn64 + nt * 8 + g;
                uint32_t B[2] = { __float_as_uint(sWhjH[(k0 + t) * SWI + n0]),
                                  __float_as_uint(sWhjH[(k0 + t + 4) * SWI + n0]) };
                MMA(O[nt], A, B);
            }
        }
        __syncthreads();
    }

    // ---- epilogue ----
    lw0 += __shfl_xor_sync(~0u, lw0, 1); lw0 += __shfl_xor_sync(~0u, lw0, 2);
    lw1 += __shfl_xor_sync(~0u, lw1, 1); lw1 += __shfl_xor_sync(~0u, lw1, 2);
    if (t == 0) { sPart[wn * 64 + r0] = lw0; sPart[wn * 64 + r1] = lw1; }
    __syncthreads();
    float inv0 = 1.f / (sPart[r0] + sPart[64 + r0] + sPart[128 + r0] + sPart[192 + r0]);
    float inv1 = 1.f / (sPart[r1] + sPart[64 + r1] + sPart[128 + r1] + sPart[192 + r1]);
    #pragma unroll
    for (int nt = 0; nt < 8; nt++) {
        int col = wn64 + nt * 8 + 2 * t;
        float o0 = O[nt][0] * inv0, o1 = O[nt][1] * inv0;
        float o2 = O[nt][2] * inv1, o3 = O[nt][3] * inv1;
        o0 = o0 > 0.f ? o0 : expm1f(o0);
        o1 = o1 > 0.f ? o1 : expm1f(o1);
        o2 = o2 > 0.f ? o2 : expm1f(o2);
        o3 = o3 > 0.f ? o3 : expm1f(o3);
        *(float2*)(out + (size_t)(i0 + r0) * F_OUT + col) = make_float2(o0, o1);
        *(float2*)(out + (size_t)(i0 + r1) * F_OUT + col) = make_float2(o2, o3);
    }
}

// ---------------- launcher ----------------
extern "C" void kernel_launch(void* const* d_in, const int* in_sizes, int n_in,
                              void* d_out, int out_size) {
    const float* h   = (const float*)d_in[0];
    const float* W   = (const float*)d_in[1];
    const float* Mui = (const float*)d_in[2];
    const int*   adj = (const int*)d_in[3];
    float* out = (float*)d_out;
    (void)in_sizes; (void)n_in; (void)out_size;

    cudaFuncSetAttribute(flash_mma, cudaFuncAttributeMaxDynamicSharedMemorySize,
                         SMEM_FLASH);

    mui_kernel<<<1, 32>>>(Mui);
    wh_gemm<<<dim3(2, 64), 256>>>(h, W);
    node_prep<<<N_NODES / 256, 256>>>();
    flash_mma<<<N_NODES / 64, 512, SMEM_FLASH>>>(adj, out);
}

// round 12
// speedup vs baseline: 4.7707x; 1.9194x over previous
#include <cuda_runtime.h>
#include <math.h>
#include <stdint.h>

#define N_NODES 8192
#define F_IN    512
#define F_OUT   256
#define NEG_MASK (-9e15f)

__device__ float g_Wh[N_NODES * F_OUT];     // exact f32 (node_prep)
__device__ float g_WhHp[N_NODES * F_OUT];   // tf32 hi, pair-packed (k,k+4) within 8-groups
__device__ float g_u[N_NODES], g_v[N_NODES], g_p[N_NODES], g_q[N_NODES];
__device__ float g_coef[4];

__device__ __forceinline__ uint32_t smem_u32(const void* p) {
    uint32_t a;
    asm("{ .reg .u64 t; cvta.to.shared.u64 t, %1; cvt.u32.u64 %0, t; }" : "=r"(a) : "l"(p));
    return a;
}
__device__ __forceinline__ uint32_t f2tf(float x) {
    uint32_t u; asm("cvt.rna.tf32.f32 %0, %1;" : "=r"(u) : "f"(x)); return u;
}
#define MMA(c, A, B) \
    asm volatile("mma.sync.aligned.m16n8k8.row.col.f32.tf32.tf32.f32 " \
        "{%0,%1,%2,%3},{%4,%5,%6,%7},{%8,%9},{%0,%1,%2,%3};" \
        : "+f"((c)[0]), "+f"((c)[1]), "+f"((c)[2]), "+f"((c)[3]) \
        : "r"((A)[0]), "r"((A)[1]), "r"((A)[2]), "r"((A)[3]), \
          "r"((B)[0]), "r"((B)[1]))
#define CP_ASYNC16(saddr, g) \
    asm volatile("cp.async.cg.shared.global [%0], [%1], 16;" :: "r"(saddr), "l"(g))
#define CP_COMMIT() asm volatile("cp.async.commit_group;")
#define CP_WAIT0()  asm volatile("cp.async.wait_group 0;")

// ---------------- kernel 1: softmax(Mui) ----------------
__global__ void mui_kernel(const float* __restrict__ Mui) {
    if (threadIdx.x == 0 && blockIdx.x == 0) {
        float m = -INFINITY;
        for (int i = 0; i < 6; i++) m = fmaxf(m, Mui[i]);
        float w[6], s = 0.f;
        for (int i = 0; i < 6; i++) { w[i] = expf(Mui[i] - m); s += w[i]; }
        float inv = 1.f / s;
        for (int i = 0; i < 6; i++) w[i] *= inv;
        g_coef[0] = w[0] + w[1] + w[2] + w[3];
        g_coef[1] = 0.5f * (w[0] + w[1]) + (w[2] + w[3]);
        g_coef[2] = 256.0f * w[4];
        g_coef[3] = 256.0f * w[5];
    }
}

// ---------------- kernel 2: Wh = h @ W; emit f32 + pair-packed tf32 hi ----------------
__global__ __launch_bounds__(256) void wh_gemm(const float* __restrict__ h,
                                               const float* __restrict__ W) {
    __shared__ float sA[16][128];
    __shared__ float sB[16][128];
    const int tid = threadIdx.x, tx = tid & 15, ty = tid >> 4;
    const int n0 = blockIdx.x * 128, m0 = blockIdx.y * 128;
    float acc[8][8];
    #pragma unroll
    for (int i = 0; i < 8; i++)
        #pragma unroll
        for (int j = 0; j < 8; j++) acc[i][j] = 0.f;
    for (int k0 = 0; k0 < F_IN; k0 += 16) {
        #pragma unroll
        for (int l = 0; l < 2; l++) {
            int idx = tid + l * 256;
            int row = idx >> 2, kq = idx & 3;
            float4 a = *(const float4*)&h[(size_t)(m0 + row) * F_IN + k0 + kq * 4];
            sA[kq * 4 + 0][row] = a.x; sA[kq * 4 + 1][row] = a.y;
            sA[kq * 4 + 2][row] = a.z; sA[kq * 4 + 3][row] = a.w;
            int rowb = idx >> 5, cq = idx & 31;
            *(float4*)&sB[rowb][cq * 4] =
                *(const float4*)&W[(size_t)(k0 + rowb) * F_OUT + n0 + cq * 4];
        }
        __syncthreads();
        #pragma unroll
        for (int k = 0; k < 16; k++) {
            float a[8], b[8];
            *(float4*)(a) = *(float4*)&sA[k][ty * 8];
            *(float4*)(a + 4) = *(float4*)&sA[k][ty * 8 + 4];
            *(float4*)(b) = *(float4*)&sB[k][tx * 8];
            *(float4*)(b + 4) = *(float4*)&sB[k][tx * 8 + 4];
            #pragma unroll
            for (int i = 0; i < 8; i++)
                #pragma unroll
                for (int j = 0; j < 8; j++) acc[i][j] = fmaf(a[i], b[j], acc[i][j]);
        }
        __syncthreads();
    }
    #pragma unroll
    for (int i = 0; i < 8; i++) {
        size_t rowb = (size_t)(m0 + ty * 8 + i) * F_OUT;
        #pragma unroll
        for (int j4 = 0; j4 < 2; j4++) {
            size_t base = rowb + n0 + tx * 8 + j4 * 4;
            float4 v = *(float4*)&acc[i][j4 * 4];
            *(float4*)&g_Wh[base] = v;
            // pair-packed tf32 hi: within 8-group, k -> (k&3)*2 + (k>>2)
            size_t pb = rowb + n0 + tx * 8;
            g_WhHp[pb + 0 * 2 + j4] = __uint_as_float(f2tf(v.x));
            g_WhHp[pb + 1 * 2 + j4] = __uint_as_float(f2tf(v.y));
            g_WhHp[pb + 2 * 2 + j4] = __uint_as_float(f2tf(v.z));
            g_WhHp[pb + 3 * 2 + j4] = __uint_as_float(f2tf(v.w));
        }
    }
}

// ---------------- kernel 3: per-node factors ----------------
__global__ void node_prep() {
    int i = blockIdx.x * blockDim.x + threadIdx.x;
    if (i < N_NODES) {
        float wh1 = g_Wh[(size_t)i * F_OUT + 1];
        float t1 = wh1 * wh1;
        g_u[i] = expf(0.5f * t1);
        g_v[i] = expf(t1);
        g_p[i] = g_coef[2] * expf(-0.5f * t1);
        g_q[i] = g_coef[3] * expf(-t1);
    }
}

// ---------------- kernel 4: flash (1xTF32 S, packed frags, cp.async) ----------------
// 512 thr, 16 warps: wm=wid&3 (16-row strip), wn=wid>>2 (16 S-cols / 64 O-cols).
#define SWP 264   // packed tile stride (floats); u64 stride 132 -> 4g+t banks
#define SPJ 68    // P stride
#define OFF_WHJ0 16896
#define OFF_WHJ1 33792
#define OFF_P    50688
#define OFF_PART 55040
#define SMEM_FLASH (55296 * 4)

__global__ __launch_bounds__(512, 1) void flash_mma(const int* __restrict__ adj,
                                                    float* __restrict__ out) {
    extern __shared__ float sm[];
    const uint32_t sb = smem_u32(sm);
    float* sP = sm + OFF_P;
    float* sPart = sm + OFF_PART;

    const int tid = threadIdx.x, lane = tid & 31, wid = tid >> 5;
    const int wm = wid & 3, wn = wid >> 2;
    const int g = lane >> 2, t = lane & 3;
    const int i0 = blockIdx.x * 64;
    const int r0 = wm * 16 + g, r1 = r0 + 8;
    const int wn16 = wn * 16, wn64 = wn * 64;

    // stage Whi (packed hi) once
    for (int x = tid; x < 64 * 64; x += 512) {
        int row = x >> 6, c4 = x & 63;
        *(float4*)(sm + row * SWP + c4 * 4) =
            *(const float4*)(g_WhHp + (size_t)(i0 + row) * F_OUT + c4 * 4);
    }
    // prefetch Whj tile 0 -> buf0
    for (int x = tid; x < 64 * 64; x += 512) {
        int row = x >> 6, c4 = x & 63;
        CP_ASYNC16(sb + (OFF_WHJ0 + row * SWP + c4 * 4) * 4,
                   g_WhHp + (size_t)row * F_OUT + c4 * 4);
    }
    CP_COMMIT();

    const float cA = g_coef[0], cB = g_coef[1];
    const float pr0 = g_p[i0 + r0], qr0 = g_q[i0 + r0];
    const float pr1 = g_p[i0 + r1], qr1 = g_q[i0 + r1];
    const int* arow0 = adj + (size_t)(i0 + r0) * N_NODES;
    const int* arow1 = adj + (size_t)(i0 + r1) * N_NODES;

    // PV B feature positions (permuted pack index), per nt
    int fp[8];
    #pragma unroll
    for (int nt = 0; nt < 8; nt++) {
        int n0 = wn64 + nt * 8 + g;
        fp[nt] = (n0 >> 3) * 8 + (n0 & 3) * 2 + ((n0 >> 2) & 1);
    }

    float O[8][4];
    #pragma unroll
    for (int n = 0; n < 8; n++) { O[n][0] = O[n][1] = O[n][2] = O[n][3] = 0.f; }
    float lw0 = 0.f, lw1 = 0.f, m0 = -INFINITY, m1 = -INFINITY;

    CP_WAIT0();
    __syncthreads();

    const uint2* aRow0 = (const uint2*)sm + r0 * 132;
    const uint2* aRow1 = (const uint2*)sm + r1 * 132;

    for (int tt = 0; tt < 128; tt++) {
        const int b = tt & 1;
        const int j0 = tt * 64;
        const float* whj = sm + (b ? OFF_WHJ1 : OFF_WHJ0);
        const uint2* bBase = (const uint2*)whj;

        if (tt < 127) {   // prefetch next into other buffer
            int joff = (b ? OFF_WHJ0 : OFF_WHJ1);
            for (int x = tid; x < 64 * 64; x += 512) {
                int row = x >> 6, c4 = x & 63;
                CP_ASYNC16(sb + (joff + row * SWP + c4 * 4) * 4,
                           g_WhHp + (size_t)(j0 + 64 + row) * F_OUT + c4 * 4);
            }
            CP_COMMIT();
        }

        // ---- S = Whi . Whj^T (1xTF32, packed LDS.64 frags) ----
        float sS[2][4];
        sS[0][0] = sS[0][1] = sS[0][2] = sS[0][3] = 0.f;
        sS[1][0] = sS[1][1] = sS[1][2] = sS[1][3] = 0.f;
        const uint2* b0 = bBase + (wn16 + g) * 132;
        const uint2* b1 = bBase + (wn16 + 8 + g) * 132;
        #pragma unroll 8
        for (int ks = 0; ks < 32; ks++) {
            int po = ks * 4 + t;
            uint2 A0 = aRow0[po], A1 = aRow1[po];
            uint32_t A[4] = { A0.x, A1.x, A0.y, A1.y };
            uint2 Bv0 = b0[po];
            uint32_t B0[2] = { Bv0.x, Bv0.y };
            MMA(sS[0], A, B0);
            uint2 Bv1 = b1[po];
            uint32_t B1[2] = { Bv1.x, Bv1.y };
            MMA(sS[1], A, B1);
        }

        // ---- logits + row max ----
        float e[2][4];
        float rm0 = -INFINITY, rm1 = -INFINITY;
        #pragma unroll
        for (int nt = 0; nt < 2; nt++) {
            int jl = wn16 + nt * 8 + 2 * t;
            float2 uu = *(const float2*)(g_u + j0 + jl);
            float2 vv = *(const float2*)(g_v + j0 + jl);
            int2 a0 = *(const int2*)(arow0 + j0 + jl);
            int2 a1 = *(const int2*)(arow1 + j0 + jl);
            e[nt][0] = a0.x > 0 ? fmaf(cA, sS[nt][0], cB) + fmaf(pr0, uu.x, qr0 * vv.x) : NEG_MASK;
            e[nt][1] = a0.y > 0 ? fmaf(cA, sS[nt][1], cB) + fmaf(pr0, uu.y, qr0 * vv.y) : NEG_MASK;
            e[nt][2] = a1.x > 0 ? fmaf(cA, sS[nt][2], cB) + fmaf(pr1, uu.x, qr1 * vv.x) : NEG_MASK;
            e[nt][3] = a1.y > 0 ? fmaf(cA, sS[nt][3], cB) + fmaf(pr1, uu.y, qr1 * vv.y) : NEG_MASK;
            rm0 = fmaxf(rm0, fmaxf(e[nt][0], e[nt][1]));
            rm1 = fmaxf(rm1, fmaxf(e[nt][2], e[nt][3]));
        }
        rm0 = fmaxf(rm0, __shfl_xor_sync(~0u, rm0, 1));
        rm0 = fmaxf(rm0, __shfl_xor_sync(~0u, rm0, 2));
        rm1 = fmaxf(rm1, __shfl_xor_sync(~0u, rm1, 1));
        rm1 = fmaxf(rm1, __shfl_xor_sync(~0u, rm1, 2));
        if (t == 0) { sPart[wn * 64 + r0] = rm0; sPart[wn * 64 + r1] = rm1; }
        __syncthreads();

        // ---- m/scale in registers (computed redundantly by every thread) ----
        float mn0 = fmaxf(fmaxf(sPart[r0], sPart[64 + r0]),
                          fmaxf(sPart[128 + r0], sPart[192 + r0]));
        float mn1 = fmaxf(fmaxf(sPart[r1], sPart[64 + r1]),
                          fmaxf(sPart[128 + r1], sPart[192 + r1]));
        mn0 = fmaxf(m0, mn0);
        mn1 = fmaxf(m1, mn1);
        float sc0 = __expf(m0 - mn0), sc1 = __expf(m1 - mn1);
        m0 = mn0; m1 = mn1;
        lw0 *= sc0; lw1 *= sc1;
        #pragma unroll
        for (int n = 0; n < 8; n++) {
            O[n][0] *= sc0; O[n][1] *= sc0; O[n][2] *= sc1; O[n][3] *= sc1;
        }
        uint32_t* sPu = (uint32_t*)sP;
        #pragma unroll
        for (int nt = 0; nt < 2; nt++) {
            int jl = wn16 + nt * 8 + 2 * t;
            uint32_t q0 = f2tf(__expf(e[nt][0] - m0));
            uint32_t q1 = f2tf(__expf(e[nt][1] - m0));
            uint32_t q2 = f2tf(__expf(e[nt][2] - m1));
            uint32_t q3 = f2tf(__expf(e[nt][3] - m1));
            lw0 += __uint_as_float(q0) + __uint_as_float(q1);
            lw1 += __uint_as_float(q2) + __uint_as_float(q3);
            *(uint2*)(sPu + r0 * SPJ + jl) = make_uint2(q0, q1);
            *(uint2*)(sPu + r1 * SPJ + jl) = make_uint2(q2, q3);
        }
        __syncthreads();

        // ---- O += P . Whj (1xTF32) ----
        const uint32_t* p0 = (const uint32_t*)sP + r0 * SPJ;
        const uint32_t* p1 = (const uint32_t*)sP + r1 * SPJ;
        #pragma unroll
        for (int ks = 0; ks < 8; ks++) {
            int k0 = ks * 8;
            uint32_t A[4] = { p0[k0 + t], p1[k0 + t], p0[k0 + t + 4], p1[k0 + t + 4] };
            #pragma unroll
            for (int nt = 0; nt < 8; nt++) {
                uint32_t B[2] = { __float_as_uint(whj[(k0 + t) * SWP + fp[nt]]),
                                  __float_as_uint(whj[(k0 + t + 4) * SWP + fp[nt]]) };
                MMA(O[nt], A, B);
            }
        }
        CP_WAIT0();
        __syncthreads();
    }

    // ---- epilogue ----
    lw0 += __shfl_xor_sync(~0u, lw0, 1); lw0 += __shfl_xor_sync(~0u, lw0, 2);
    lw1 += __shfl_xor_sync(~0u, lw1, 1); lw1 += __shfl_xor_sync(~0u, lw1, 2);
    if (t == 0) { sPart[wn * 64 + r0] = lw0; sPart[wn * 64 + r1] = lw1; }
    __syncthreads();
    float inv0 = 1.f / (sPart[r0] + sPart[64 + r0] + sPart[128 + r0] + sPart[192 + r0]);
    float inv1 = 1.f / (sPart[r1] + sPart[64 + r1] + sPart[128 + r1] + sPart[192 + r1]);
    #pragma unroll
    for (int nt = 0; nt < 8; nt++) {
        int col = wn64 + nt * 8 + 2 * t;
        float o0 = O[nt][0] * inv0, o1 = O[nt][1] * inv0;
        float o2 = O[nt][2] * inv1, o3 = O[nt][3] * inv1;
        o0 = o0 > 0.f ? o0 : expm1f(o0);
        o1 = o1 > 0.f ? o1 : expm1f(o1);
        o2 = o2 > 0.f ? o2 : expm1f(o2);
        o3 = o3 > 0.f ? o3 : expm1f(o3);
        *(float2*)(out + (size_t)(i0 + r0) * F_OUT + col) = make_float2(o0, o1);
        *(float2*)(out + (size_t)(i0 + r1) * F_OUT + col) = make_float2(o2, o3);
    }
}

// ---------------- launcher ----------------
extern "C" void kernel_launch(void* const* d_in, const int* in_sizes, int n_in,
                              void* d_out, int out_size) {
    const float* h   = (const float*)d_in[0];
    const float* W   = (const float*)d_in[1];
    const float* Mui = (const float*)d_in[2];
    const int*   adj = (const int*)d_in[3];
    float* out = (float*)d_out;
    (void)in_sizes; (void)n_in; (void)out_size;

    cudaFuncSetAttribute(flash_mma, cudaFuncAttributeMaxDynamicSharedMemorySize,
                         SMEM_FLASH);

    mui_kernel<<<1, 32>>>(Mui);
    wh_gemm<<<dim3(2, 64), 256>>>(h, W);
    node_prep<<<N_NODES / 256, 256>>>();
    flash_mma<<<N_NODES / 64, 512, SMEM_FLASH>>>(adj, out);
}